// round 1
// baseline (speedup 1.0000x reference)
#include <cuda_runtime.h>

#define Bdim 8
#define Ndim 512
#define Pdim 16
#define Cdim 512
#define Hdim 8
#define HD   64
#define BN   (Bdim*Ndim)      /* 4096  */
#define BNP  (BN*Pdim)        /* 65536 */
#define BH   (Bdim*Hdim)      /* 64    */
#define EP   (HD*Pdim)        /* 1024  */

// ---------------- scratch (single __device__ buffer, no allocations) --------
#define OFF_XQ 0ull
#define OFF_XK (OFF_XQ + (size_t)BN*Cdim)
#define OFF_Q  (OFF_XK + (size_t)BN*Cdim)
#define OFF_K  (OFF_Q  + (size_t)BN*Cdim)
#define OFF_V  (OFF_K  + (size_t)BN*Cdim)
#define OFF_VP (OFF_V  + (size_t)BNP*Cdim)
#define OFF_S  (OFF_VP + (size_t)BNP*Cdim)
#define OFF_O2 (OFF_S  + (size_t)BH*Ndim*Ndim)
#define OFF_O  (OFF_O2 + (size_t)BNP*Cdim)
#define SCRATCH_FLOATS (OFF_O + (size_t)BNP*Cdim)

__device__ float g_scratch[SCRATCH_FLOATS];

// ---------------- prep: xq = x[:,:,0,:], xk = masked mean over P ------------
__global__ void prep_kernel(const float* __restrict__ x,
                            const float* __restrict__ mask,
                            float* __restrict__ xq, float* __restrict__ xk) {
    int bn = blockIdx.x;          // 0..4095
    int c  = threadIdx.x;         // 0..511
    const float* xb = x + (size_t)bn * Pdim * Cdim;
    const float* mb = mask + (size_t)bn * Pdim;
    float cnt = 0.f, s = 0.f;
#pragma unroll
    for (int p = 0; p < Pdim; p++) {
        float m = mb[p];
        cnt += m;
        s += m * xb[(size_t)p * Cdim + c];
    }
    xq[(size_t)bn * Cdim + c] = xb[c];
    xk[(size_t)bn * Cdim + c] = s / cnt;
}

// ---------------- generic batched SGEMM: C = A @ B (+bias) ------------------
// 128x128 tile, BK=16, 256 threads, 8x8 per thread. M, N multiples of 128,
// K multiple of 16, lda/ldb/ldc multiples of 4.
__global__ void __launch_bounds__(256)
sgemm_kernel(const float* __restrict__ A, int lda, size_t sA,
             const float* __restrict__ Bm, int ldb, size_t sB,
             float* __restrict__ Cm, int ldc, size_t sC,
             int K, const float* __restrict__ bias) {
    int bz = blockIdx.z;
    A  += (size_t)bz * sA;
    Bm += (size_t)bz * sB;
    Cm += (size_t)bz * sC;

    __shared__ float As[16][128];
    __shared__ float Bs[16][128];

    int tid = threadIdx.x;
    int tx = tid & 15, ty = tid >> 4;
    size_t row0 = (size_t)blockIdx.y * 128;
    int col0 = blockIdx.x * 128;

    float acc[8][8];
#pragma unroll
    for (int i = 0; i < 8; i++)
#pragma unroll
        for (int j = 0; j < 8; j++) acc[i][j] = 0.f;

    int a_m = tid >> 2;            // 0..63
    int a_k = (tid & 3) * 4;       // 0,4,8,12
    int b_k = tid >> 5;            // 0..7
    int b_n = (tid & 31) * 4;      // 0..124

    for (int k0 = 0; k0 < K; k0 += 16) {
        float4 av0 = *(const float4*)&A[(row0 + a_m) * lda + k0 + a_k];
        float4 av1 = *(const float4*)&A[(row0 + a_m + 64) * lda + k0 + a_k];
        float4 bv0 = *(const float4*)&Bm[(size_t)(k0 + b_k) * ldb + col0 + b_n];
        float4 bv1 = *(const float4*)&Bm[(size_t)(k0 + b_k + 8) * ldb + col0 + b_n];

        As[a_k + 0][a_m] = av0.x; As[a_k + 1][a_m] = av0.y;
        As[a_k + 2][a_m] = av0.z; As[a_k + 3][a_m] = av0.w;
        As[a_k + 0][a_m + 64] = av1.x; As[a_k + 1][a_m + 64] = av1.y;
        As[a_k + 2][a_m + 64] = av1.z; As[a_k + 3][a_m + 64] = av1.w;
        *(float4*)&Bs[b_k][b_n]     = bv0;
        *(float4*)&Bs[b_k + 8][b_n] = bv1;
        __syncthreads();

#pragma unroll
        for (int k = 0; k < 16; k++) {
            float4 a0 = *(const float4*)&As[k][ty * 4];
            float4 a1 = *(const float4*)&As[k][ty * 4 + 64];
            float4 b0 = *(const float4*)&Bs[k][tx * 4];
            float4 b1 = *(const float4*)&Bs[k][tx * 4 + 64];
            float ar[8] = {a0.x, a0.y, a0.z, a0.w, a1.x, a1.y, a1.z, a1.w};
            float br[8] = {b0.x, b0.y, b0.z, b0.w, b1.x, b1.y, b1.z, b1.w};
#pragma unroll
            for (int i = 0; i < 8; i++)
#pragma unroll
                for (int j = 0; j < 8; j++) acc[i][j] += ar[i] * br[j];
        }
        __syncthreads();
    }

#pragma unroll
    for (int i = 0; i < 8; i++) {
        size_t row = row0 + ((i < 4) ? (ty * 4 + i) : (64 + ty * 4 + i - 4));
#pragma unroll
        for (int jm = 0; jm < 2; jm++) {
            int col = col0 + jm * 64 + tx * 4;
            float4 rv;
            rv.x = acc[i][jm * 4 + 0]; rv.y = acc[i][jm * 4 + 1];
            rv.z = acc[i][jm * 4 + 2]; rv.w = acc[i][jm * 4 + 3];
            if (bias) {
                rv.x += bias[col + 0]; rv.y += bias[col + 1];
                rv.z += bias[col + 2]; rv.w += bias[col + 3];
            }
            *(float4*)&Cm[row * ldc + col] = rv;
        }
    }
}

// ---------------- scores: S[bh,n,m] = scale * Q_bh[n,:] . K_bh[m,:] ---------
__global__ void __launch_bounds__(256)
scores_kernel(const float* __restrict__ Q, const float* __restrict__ Kt,
              float* __restrict__ S) {
    int bh = blockIdx.z;
    int b = bh >> 3, h = bh & 7;
    const float* Qb = Q + (size_t)b * Ndim * Cdim + h * HD;
    const float* Kb = Kt + (size_t)b * Ndim * Cdim + h * HD;
    float* Sb = S + (size_t)bh * Ndim * Ndim;

    __shared__ float Qs[64][68];
    __shared__ float Ks[64][68];

    int tid = threadIdx.x, tx = tid & 15, ty = tid >> 4;
    int n0 = blockIdx.y * 64, m0 = blockIdx.x * 64;
    int lr = tid >> 4;            // 0..15
    int ld = (tid & 15) * 4;      // 0..60

#pragma unroll
    for (int i = 0; i < 4; i++) {
        int r = lr + i * 16;
        float4 q = *(const float4*)&Qb[(size_t)(n0 + r) * Cdim + ld];
        float4 k = *(const float4*)&Kb[(size_t)(m0 + r) * Cdim + ld];
        Qs[r][ld] = q.x; Qs[r][ld + 1] = q.y; Qs[r][ld + 2] = q.z; Qs[r][ld + 3] = q.w;
        Ks[r][ld] = k.x; Ks[r][ld + 1] = k.y; Ks[r][ld + 2] = k.z; Ks[r][ld + 3] = k.w;
    }
    __syncthreads();

    float acc[4][4];
#pragma unroll
    for (int i = 0; i < 4; i++)
#pragma unroll
        for (int j = 0; j < 4; j++) acc[i][j] = 0.f;

#pragma unroll
    for (int d = 0; d < 64; d++) {
        float a[4], bb[4];
#pragma unroll
        for (int i = 0; i < 4; i++) a[i] = Qs[ty * 4 + i][d];
#pragma unroll
        for (int j = 0; j < 4; j++) bb[j] = Ks[tx * 4 + j][d];
#pragma unroll
        for (int i = 0; i < 4; i++)
#pragma unroll
            for (int j = 0; j < 4; j++) acc[i][j] += a[i] * bb[j];
    }

    const float scale = 0.125f;   // 1/sqrt(64)
#pragma unroll
    for (int i = 0; i < 4; i++) {
        float4 rv;
        rv.x = acc[i][0] * scale; rv.y = acc[i][1] * scale;
        rv.z = acc[i][2] * scale; rv.w = acc[i][3] * scale;
        *(float4*)&Sb[(size_t)(n0 + ty * 4 + i) * Ndim + m0 + tx * 4] = rv;
    }
}

// ---------------- softmax over last dim (row length 512) --------------------
__global__ void __launch_bounds__(256)
softmax_kernel(float* __restrict__ S) {
    float* r = S + (size_t)blockIdx.x * Ndim;
    int tid = threadIdx.x;
    float v0 = r[tid], v1 = r[tid + 256];

    __shared__ float red[8];
    unsigned full = 0xffffffffu;

    float m = fmaxf(v0, v1);
#pragma unroll
    for (int o = 16; o; o >>= 1) m = fmaxf(m, __shfl_xor_sync(full, m, o));
    if ((tid & 31) == 0) red[tid >> 5] = m;
    __syncthreads();
    float mm = fmaxf(fmaxf(fmaxf(red[0], red[1]), fmaxf(red[2], red[3])),
                     fmaxf(fmaxf(red[4], red[5]), fmaxf(red[6], red[7])));
    __syncthreads();

    float e0 = __expf(v0 - mm), e1 = __expf(v1 - mm);
    float s = e0 + e1;
#pragma unroll
    for (int o = 16; o; o >>= 1) s += __shfl_xor_sync(full, s, o);
    if ((tid & 31) == 0) red[tid >> 5] = s;
    __syncthreads();
    float ss = red[0] + red[1] + red[2] + red[3] + red[4] + red[5] + red[6] + red[7];
    float inv = 1.0f / ss;
    r[tid] = e0 * inv;
    r[tid + 256] = e1 * inv;
}

// ---------------- pack V: Vp[bh, m, d*16+p] = V[b, m, p, h*64+d] ------------
__global__ void __launch_bounds__(256)
packV_kernel(const float* __restrict__ V, float* __restrict__ Vp) {
    int blk = blockIdx.x;              // bh*512 + m
    int m = blk & 511, bh = blk >> 9;
    int b = bh >> 3, h = bh & 7;
    const float* src = V + (size_t)(b * Ndim + m) * Pdim * Cdim + h * HD;
    float* dst = Vp + (size_t)blk * EP;

    __shared__ float tile[Pdim][HD];
    int tid = threadIdx.x;
    int p = tid >> 4, d = (tid & 15) * 4;
    float4 v = *(const float4*)&src[(size_t)p * Cdim + d];
    tile[p][d] = v.x; tile[p][d + 1] = v.y; tile[p][d + 2] = v.z; tile[p][d + 3] = v.w;
    __syncthreads();

    int e0 = tid * 4;
    float4 o;
    o.x = tile[(e0 + 0) & 15][(e0 + 0) >> 4];
    o.y = tile[(e0 + 1) & 15][(e0 + 1) >> 4];
    o.z = tile[(e0 + 2) & 15][(e0 + 2) >> 4];
    o.w = tile[(e0 + 3) & 15][(e0 + 3) >> 4];
    *(float4*)&dst[e0] = o;
}

// ---------------- unpack O: O[b,n,p,h*64+d] = O2[bh, n, d*16+p] -------------
__global__ void __launch_bounds__(256)
unpackO_kernel(const float* __restrict__ O2, float* __restrict__ O) {
    int blk = blockIdx.x;              // bh*512 + n
    int n = blk & 511, bh = blk >> 9;
    int b = bh >> 3, h = bh & 7;
    const float* src = O2 + (size_t)blk * EP;
    float* dst = O + (size_t)(b * Ndim + n) * Pdim * Cdim + h * HD;

    __shared__ float tile[EP];
    int tid = threadIdx.x;
    *(float4*)&tile[tid * 4] = *(const float4*)&src[tid * 4];
    __syncthreads();

    int p = tid >> 4, d = (tid & 15) * 4;
    float4 o;
    o.x = tile[(d + 0) * 16 + p];
    o.y = tile[(d + 1) * 16 + p];
    o.z = tile[(d + 2) * 16 + p];
    o.w = tile[(d + 3) * 16 + p];
    *(float4*)&dst[(size_t)p * Cdim + d] = o;
}

// ---------------------------------------------------------------------------
extern "C" void kernel_launch(void* const* d_in, const int* in_sizes, int n_in,
                              void* d_out, int out_size) {
    const float* x     = (const float*)d_in[0];
    const float* mask  = (const float*)d_in[1];
    // d_in[2] = lens (unused), d_in[3] = lens_mask (unused)
    const float* Wqkv  = (const float*)d_in[4];
    const float* Wproj = (const float*)d_in[5];
    const float* bproj = (const float*)d_in[6];
    float* out = (float*)d_out;

    float* scratch = nullptr;
    cudaGetSymbolAddress((void**)&scratch, g_scratch);
    float* xq = scratch + OFF_XQ;
    float* xk = scratch + OFF_XK;
    float* Qb = scratch + OFF_Q;
    float* Kb = scratch + OFF_K;
    float* Vb = scratch + OFF_V;
    float* Vp = scratch + OFF_VP;
    float* Sb = scratch + OFF_S;
    float* O2 = scratch + OFF_O2;
    float* Ob = scratch + OFF_O;

    // 1. masked-mean / slot-0 extract
    prep_kernel<<<BN, Cdim>>>(x, mask, xq, xk);

    // 2. Q = xq @ Wq, K = xk @ Wk   (4096x512x512 each)
    sgemm_kernel<<<dim3(Cdim / 128, BN / 128, 1), 256>>>(
        xq, Cdim, 0, Wqkv, 3 * Cdim, 0, Qb, Cdim, 0, Cdim, nullptr);
    sgemm_kernel<<<dim3(Cdim / 128, BN / 128, 1), 256>>>(
        xk, Cdim, 0, Wqkv + Cdim, 3 * Cdim, 0, Kb, Cdim, 0, Cdim, nullptr);

    // 3. V = x @ Wv   (65536x512x512)
    sgemm_kernel<<<dim3(Cdim / 128, BNP / 128, 1), 256>>>(
        x, Cdim, 0, Wqkv + 2 * Cdim, 3 * Cdim, 0, Vb, Cdim, 0, Cdim, nullptr);

    // 4. pack V to [bh, m, hd*P]
    packV_kernel<<<BH * Ndim, 256>>>(Vb, Vp);

    // 5. scores S = scale * Q K^T  (per bh)
    scores_kernel<<<dim3(Ndim / 64, Ndim / 64, BH), 256>>>(Qb, Kb, Sb);

    // 6. softmax rows
    softmax_kernel<<<BH * Ndim, 256>>>(Sb);

    // 7. O2 = S @ Vp  (batched 64: 512x1024x512)
    sgemm_kernel<<<dim3(EP / 128, Ndim / 128, BH), 256>>>(
        Sb, Ndim, (size_t)Ndim * Ndim,
        Vp, EP, (size_t)Ndim * EP,
        O2, EP, (size_t)Ndim * EP, Ndim, nullptr);

    // 8. unpack O2 -> [b,n,p,c]
    unpackO_kernel<<<BH * Ndim, 256>>>(O2, Ob);

    // 9. out = O @ Wproj + bproj  (65536x512x512)
    sgemm_kernel<<<dim3(Cdim / 128, BNP / 128, 1), 256>>>(
        Ob, Cdim, 0, Wproj, Cdim, 0, out, Cdim, 0, Cdim, bproj);
}

// round 2
// speedup vs baseline: 2.4875x; 2.4875x over previous
#include <cuda_runtime.h>
#include <cstdint>

#define Bdim 8
#define Ndim 512
#define Pdim 16
#define Cdim 512
#define Hdim 8
#define HD   64
#define BN   (Bdim*Ndim)      /* 4096  */
#define BNP  (BN*Pdim)        /* 65536 */
#define BH   (Bdim*Hdim)      /* 64    */
#define EP   (HD*Pdim)        /* 1024  */

// ---------------- scratch (single __device__ buffer, no allocations) --------
#define OFF_XQ 0ull
#define OFF_XK (OFF_XQ + (size_t)BN*Cdim)
#define OFF_Q  (OFF_XK + (size_t)BN*Cdim)
#define OFF_K  (OFF_Q  + (size_t)BN*Cdim)
#define OFF_V  (OFF_K  + (size_t)BN*Cdim)
#define OFF_VP (OFF_V  + (size_t)BNP*Cdim)
#define OFF_S  (OFF_VP + (size_t)BNP*Cdim)
#define OFF_O2 (OFF_S  + (size_t)BH*Ndim*Ndim)
#define OFF_O  (OFF_O2 + (size_t)BNP*Cdim)
#define SCRATCH_FLOATS (OFF_O + (size_t)BNP*Cdim)

__device__ float g_scratch[SCRATCH_FLOATS];

__device__ __forceinline__ uint32_t f2tf(float f) {
    uint32_t u;
    asm("cvt.rna.tf32.f32 %0, %1;" : "=r"(u) : "f"(f));
    return u;
}

// ---------------- prep: xq = x[:,:,0,:], xk = masked mean over P ------------
__global__ void prep_kernel(const float* __restrict__ x,
                            const float* __restrict__ mask,
                            float* __restrict__ xq, float* __restrict__ xk) {
    int bn = blockIdx.x;
    int c  = threadIdx.x;
    const float* xb = x + (size_t)bn * Pdim * Cdim;
    const float* mb = mask + (size_t)bn * Pdim;
    float cnt = 0.f, s = 0.f;
#pragma unroll
    for (int p = 0; p < Pdim; p++) {
        float m = mb[p];
        cnt += m;
        s += m * xb[(size_t)p * Cdim + c];
    }
    xq[(size_t)bn * Cdim + c] = xb[c];
    xk[(size_t)bn * Cdim + c] = s / cnt;
}

// ---------------- tf32 tensor-core GEMM: C = A @ B (+bias) ------------------
// 128x128 tile, BK=32, 256 threads (8 warps, 2x4 grid, 64x32 warp tile),
// m16n8k8 tf32 mma.sync. M,N multiples of 128, K multiple of 32.
__global__ void __launch_bounds__(256)
tgemm_kernel(const float* __restrict__ A, int lda, size_t sA,
             const float* __restrict__ Bm, int ldb, size_t sB,
             float* __restrict__ Cm, int ldc, size_t sC,
             int K, const float* __restrict__ bias) {
    int bz = blockIdx.z;
    A  += (size_t)bz * sA;
    Bm += (size_t)bz * sB;
    Cm += (size_t)bz * sC;

    // pads chosen for conflict-free fragment loads:
    // As: bank = (36m+k)%32 = (4m+k)%32 -> g(8) x tig(4) all distinct
    // Bs: bank = (136k+n)%32 = (8k+n)%32 -> tig(4) x g(8) all distinct
    __shared__ uint32_t As[128][36];
    __shared__ uint32_t Bs[32][136];

    const int tid  = threadIdx.x;
    const int lane = tid & 31, warp = tid >> 5;
    const int g    = lane >> 2, tig = lane & 3;
    const int wm   = (warp >> 2) * 64;   // 0 or 64
    const int wn   = (warp & 3) * 32;    // 0,32,64,96
    const size_t row0 = (size_t)blockIdx.y * 128;
    const int col0 = blockIdx.x * 128;

    float acc[4][4][4];
#pragma unroll
    for (int mi = 0; mi < 4; mi++)
#pragma unroll
        for (int ni = 0; ni < 4; ni++)
#pragma unroll
            for (int r = 0; r < 4; r++) acc[mi][ni][r] = 0.f;

    const int ar = tid >> 3;        // 0..31 (+32*i)
    const int ac = (tid & 7) * 4;   // 0..28 within BK
    const int br = tid >> 3;        // k-row 0..31
    const int bc = (tid & 7) * 4;   // 0..28 (+32*i)

    float4 aR[4], bR[4];
#pragma unroll
    for (int i = 0; i < 4; i++)
        aR[i] = *(const float4*)(A + (row0 + ar + 32 * i) * lda + ac);
#pragma unroll
    for (int i = 0; i < 4; i++)
        bR[i] = *(const float4*)(Bm + (size_t)br * ldb + col0 + bc + 32 * i);

    for (int k0 = 0; k0 < K; k0 += 32) {
        // stage current tile (convert to tf32)
#pragma unroll
        for (int i = 0; i < 4; i++) {
            int r = ar + 32 * i;
            As[r][ac + 0] = f2tf(aR[i].x); As[r][ac + 1] = f2tf(aR[i].y);
            As[r][ac + 2] = f2tf(aR[i].z); As[r][ac + 3] = f2tf(aR[i].w);
        }
#pragma unroll
        for (int i = 0; i < 4; i++) {
            int c = bc + 32 * i;
            Bs[br][c + 0] = f2tf(bR[i].x); Bs[br][c + 1] = f2tf(bR[i].y);
            Bs[br][c + 2] = f2tf(bR[i].z); Bs[br][c + 3] = f2tf(bR[i].w);
        }
        __syncthreads();

        // prefetch next tile into registers
        if (k0 + 32 < K) {
            int kn = k0 + 32;
#pragma unroll
            for (int i = 0; i < 4; i++)
                aR[i] = *(const float4*)(A + (row0 + ar + 32 * i) * lda + kn + ac);
#pragma unroll
            for (int i = 0; i < 4; i++)
                bR[i] = *(const float4*)(Bm + (size_t)(kn + br) * ldb + col0 + bc + 32 * i);
        }

        // compute 4 k-steps of m16n8k8
#pragma unroll
        for (int ks = 0; ks < 4; ks++) {
            const int k8 = ks * 8;
            uint32_t a[4][4], b[4][2];
#pragma unroll
            for (int mi = 0; mi < 4; mi++) {
                int m = wm + mi * 16 + g;
                a[mi][0] = As[m][k8 + tig];
                a[mi][1] = As[m + 8][k8 + tig];
                a[mi][2] = As[m][k8 + tig + 4];
                a[mi][3] = As[m + 8][k8 + tig + 4];
            }
#pragma unroll
            for (int ni = 0; ni < 4; ni++) {
                int n = wn + ni * 8 + g;
                b[ni][0] = Bs[k8 + tig][n];
                b[ni][1] = Bs[k8 + tig + 4][n];
            }
#pragma unroll
            for (int mi = 0; mi < 4; mi++)
#pragma unroll
                for (int ni = 0; ni < 4; ni++) {
                    asm volatile(
                        "mma.sync.aligned.m16n8k8.row.col.f32.tf32.tf32.f32 "
                        "{%0,%1,%2,%3}, {%4,%5,%6,%7}, {%8,%9}, {%0,%1,%2,%3};"
                        : "+f"(acc[mi][ni][0]), "+f"(acc[mi][ni][1]),
                          "+f"(acc[mi][ni][2]), "+f"(acc[mi][ni][3])
                        : "r"(a[mi][0]), "r"(a[mi][1]), "r"(a[mi][2]), "r"(a[mi][3]),
                          "r"(b[ni][0]), "r"(b[ni][1]));
                }
        }
        __syncthreads();
    }

    // epilogue: c0,c1 at (g, 2tig), c2,c3 at (g+8, 2tig)
#pragma unroll
    for (int mi = 0; mi < 4; mi++) {
        size_t r = row0 + wm + mi * 16 + g;
#pragma unroll
        for (int ni = 0; ni < 4; ni++) {
            int c = col0 + wn + ni * 8 + tig * 2;
            float bx = 0.f, by = 0.f;
            if (bias) { bx = bias[c]; by = bias[c + 1]; }
            float2 v0 = make_float2(acc[mi][ni][0] + bx, acc[mi][ni][1] + by);
            float2 v1 = make_float2(acc[mi][ni][2] + bx, acc[mi][ni][3] + by);
            *(float2*)&Cm[r * ldc + c] = v0;
            *(float2*)&Cm[(r + 8) * ldc + c] = v1;
        }
    }
}

// ---------------- scores: S[bh,n,m] = scale * Q_bh[n,:] . K_bh[m,:] ---------
__global__ void __launch_bounds__(256)
scores_kernel(const float* __restrict__ Q, const float* __restrict__ Kt,
              float* __restrict__ S) {
    int bh = blockIdx.z;
    int b = bh >> 3, h = bh & 7;
    const float* Qb = Q + (size_t)b * Ndim * Cdim + h * HD;
    const float* Kb = Kt + (size_t)b * Ndim * Cdim + h * HD;
    float* Sb = S + (size_t)bh * Ndim * Ndim;

    __shared__ float Qs[64][68];
    __shared__ float Ks[64][68];

    int tid = threadIdx.x, tx = tid & 15, ty = tid >> 4;
    int n0 = blockIdx.y * 64, m0 = blockIdx.x * 64;
    int lr = tid >> 4;
    int ld = (tid & 15) * 4;

#pragma unroll
    for (int i = 0; i < 4; i++) {
        int r = lr + i * 16;
        float4 q = *(const float4*)&Qb[(size_t)(n0 + r) * Cdim + ld];
        float4 k = *(const float4*)&Kb[(size_t)(m0 + r) * Cdim + ld];
        Qs[r][ld] = q.x; Qs[r][ld + 1] = q.y; Qs[r][ld + 2] = q.z; Qs[r][ld + 3] = q.w;
        Ks[r][ld] = k.x; Ks[r][ld + 1] = k.y; Ks[r][ld + 2] = k.z; Ks[r][ld + 3] = k.w;
    }
    __syncthreads();

    float acc[4][4];
#pragma unroll
    for (int i = 0; i < 4; i++)
#pragma unroll
        for (int j = 0; j < 4; j++) acc[i][j] = 0.f;

#pragma unroll
    for (int d = 0; d < 64; d++) {
        float a[4], bb[4];
#pragma unroll
        for (int i = 0; i < 4; i++) a[i] = Qs[ty * 4 + i][d];
#pragma unroll
        for (int j = 0; j < 4; j++) bb[j] = Ks[tx * 4 + j][d];
#pragma unroll
        for (int i = 0; i < 4; i++)
#pragma unroll
            for (int j = 0; j < 4; j++) acc[i][j] += a[i] * bb[j];
    }

    const float scale = 0.125f;
#pragma unroll
    for (int i = 0; i < 4; i++) {
        float4 rv;
        rv.x = acc[i][0] * scale; rv.y = acc[i][1] * scale;
        rv.z = acc[i][2] * scale; rv.w = acc[i][3] * scale;
        *(float4*)&Sb[(size_t)(n0 + ty * 4 + i) * Ndim + m0 + tx * 4] = rv;
    }
}

// ---------------- softmax over last dim (row length 512) --------------------
__global__ void __launch_bounds__(256)
softmax_kernel(float* __restrict__ S) {
    float* r = S + (size_t)blockIdx.x * Ndim;
    int tid = threadIdx.x;
    float v0 = r[tid], v1 = r[tid + 256];

    __shared__ float red[8];
    unsigned full = 0xffffffffu;

    float m = fmaxf(v0, v1);
#pragma unroll
    for (int o = 16; o; o >>= 1) m = fmaxf(m, __shfl_xor_sync(full, m, o));
    if ((tid & 31) == 0) red[tid >> 5] = m;
    __syncthreads();
    float mm = fmaxf(fmaxf(fmaxf(red[0], red[1]), fmaxf(red[2], red[3])),
                     fmaxf(fmaxf(red[4], red[5]), fmaxf(red[6], red[7])));
    __syncthreads();

    float e0 = __expf(v0 - mm), e1 = __expf(v1 - mm);
    float s = e0 + e1;
#pragma unroll
    for (int o = 16; o; o >>= 1) s += __shfl_xor_sync(full, s, o);
    if ((tid & 31) == 0) red[tid >> 5] = s;
    __syncthreads();
    float ss = red[0] + red[1] + red[2] + red[3] + red[4] + red[5] + red[6] + red[7];
    float inv = 1.0f / ss;
    r[tid] = e0 * inv;
    r[tid + 256] = e1 * inv;
}

// ---------------- pack V: Vp[bh, m, d*16+p] = V[b, m, p, h*64+d] ------------
__global__ void __launch_bounds__(256)
packV_kernel(const float* __restrict__ V, float* __restrict__ Vp) {
    int blk = blockIdx.x;
    int m = blk & 511, bh = blk >> 9;
    int b = bh >> 3, h = bh & 7;
    const float* src = V + (size_t)(b * Ndim + m) * Pdim * Cdim + h * HD;
    float* dst = Vp + (size_t)blk * EP;

    __shared__ float tile[Pdim][HD];
    int tid = threadIdx.x;
    int p = tid >> 4, d = (tid & 15) * 4;
    float4 v = *(const float4*)&src[(size_t)p * Cdim + d];
    tile[p][d] = v.x; tile[p][d + 1] = v.y; tile[p][d + 2] = v.z; tile[p][d + 3] = v.w;
    __syncthreads();

    int e0 = tid * 4;
    float4 o;
    o.x = tile[(e0 + 0) & 15][(e0 + 0) >> 4];
    o.y = tile[(e0 + 1) & 15][(e0 + 1) >> 4];
    o.z = tile[(e0 + 2) & 15][(e0 + 2) >> 4];
    o.w = tile[(e0 + 3) & 15][(e0 + 3) >> 4];
    *(float4*)&dst[e0] = o;
}

// ---------------- unpack O: O[b,n,p,h*64+d] = O2[bh, n, d*16+p] -------------
__global__ void __launch_bounds__(256)
unpackO_kernel(const float* __restrict__ O2, float* __restrict__ O) {
    int blk = blockIdx.x;
    int n = blk & 511, bh = blk >> 9;
    int b = bh >> 3, h = bh & 7;
    const float* src = O2 + (size_t)blk * EP;
    float* dst = O + (size_t)(b * Ndim + n) * Pdim * Cdim + h * HD;

    __shared__ float tile[EP];
    int tid = threadIdx.x;
    *(float4*)&tile[tid * 4] = *(const float4*)&src[tid * 4];
    __syncthreads();

    int p = tid >> 4, d = (tid & 15) * 4;
    float4 o;
    o.x = tile[(d + 0) * 16 + p];
    o.y = tile[(d + 1) * 16 + p];
    o.z = tile[(d + 2) * 16 + p];
    o.w = tile[(d + 3) * 16 + p];
    *(float4*)&dst[(size_t)p * Cdim + d] = o;
}

// ---------------------------------------------------------------------------
extern "C" void kernel_launch(void* const* d_in, const int* in_sizes, int n_in,
                              void* d_out, int out_size) {
    const float* x     = (const float*)d_in[0];
    const float* mask  = (const float*)d_in[1];
    const float* Wqkv  = (const float*)d_in[4];
    const float* Wproj = (const float*)d_in[5];
    const float* bproj = (const float*)d_in[6];
    float* out = (float*)d_out;

    float* scratch = nullptr;
    cudaGetSymbolAddress((void**)&scratch, g_scratch);
    float* xq = scratch + OFF_XQ;
    float* xk = scratch + OFF_XK;
    float* Qb = scratch + OFF_Q;
    float* Kb = scratch + OFF_K;
    float* Vb = scratch + OFF_V;
    float* Vp = scratch + OFF_VP;
    float* Sb = scratch + OFF_S;
    float* O2 = scratch + OFF_O2;
    float* Ob = scratch + OFF_O;

    // 1. masked-mean / slot-0 extract
    prep_kernel<<<BN, Cdim>>>(x, mask, xq, xk);

    // 2. Q = xq @ Wq, K = xk @ Wk   (4096x512x512 each, tf32 MMA)
    tgemm_kernel<<<dim3(Cdim / 128, BN / 128, 1), 256>>>(
        xq, Cdim, 0, Wqkv, 3 * Cdim, 0, Qb, Cdim, 0, Cdim, nullptr);
    tgemm_kernel<<<dim3(Cdim / 128, BN / 128, 1), 256>>>(
        xk, Cdim, 0, Wqkv + Cdim, 3 * Cdim, 0, Kb, Cdim, 0, Cdim, nullptr);

    // 3. V = x @ Wv   (65536x512x512)
    tgemm_kernel<<<dim3(Cdim / 128, BNP / 128, 1), 256>>>(
        x, Cdim, 0, Wqkv + 2 * Cdim, 3 * Cdim, 0, Vb, Cdim, 0, Cdim, nullptr);

    // 4. pack V to [bh, m, hd*P]
    packV_kernel<<<BH * Ndim, 256>>>(Vb, Vp);

    // 5. scores S = scale * Q K^T  (per bh, fp32)
    scores_kernel<<<dim3(Ndim / 64, Ndim / 64, BH), 256>>>(Qb, Kb, Sb);

    // 6. softmax rows
    softmax_kernel<<<BH * Ndim, 256>>>(Sb);

    // 7. O2 = S @ Vp  (batched 64: 512x1024x512)
    tgemm_kernel<<<dim3(EP / 128, Ndim / 128, BH), 256>>>(
        Sb, Ndim, (size_t)Ndim * Ndim,
        Vp, EP, (size_t)Ndim * EP,
        O2, EP, (size_t)Ndim * EP, Ndim, nullptr);

    // 8. unpack O2 -> [b,n,p,c]
    unpackO_kernel<<<BH * Ndim, 256>>>(O2, Ob);

    // 9. out = O @ Wproj + bproj  (65536x512x512)
    tgemm_kernel<<<dim3(Cdim / 128, BNP / 128, 1), 256>>>(
        Ob, Cdim, 0, Wproj, Cdim, 0, out, Cdim, 0, Cdim, bproj);
}